// round 3
// baseline (speedup 1.0000x reference)
#include <cuda_runtime.h>
#include <cuda_bf16.h>

#define N_NODES 100000
#define D_IN    256
#define D_OUT   128
#define NNZ     3200000

// Scratch (static device array: no allocation allowed)
__device__ float g_h[(size_t)N_NODES * D_OUT];   // 51.2 MB intermediate h = x @ W

// ---------------------------------------------------------------------------
// Threefry-2x32, JAX partitionable scheme for 32-bit draws:
// key = (0, 42); counter (hi=0, lo=i); 20 rounds; output = lane0 XOR lane1
// (matches _threefry_random_bits_partitionable: bits1 ^ bits2 for bit_width 32).
// ---------------------------------------------------------------------------
__device__ __forceinline__ unsigned int threefry_xor(unsigned int ctr) {
    const unsigned int ks0 = 0u;
    const unsigned int ks1 = 42u;
    const unsigned int ks2 = ks0 ^ ks1 ^ 0x1BD11BDAu;
    unsigned int x0 = ks0;          // ctr_hi(0) + ks0
    unsigned int x1 = ctr + ks1;    // ctr_lo(i) + ks1
#define TF_RND(r) { x0 += x1; x1 = (x1 << (r)) | (x1 >> (32 - (r))); x1 ^= x0; }
    TF_RND(13) TF_RND(15) TF_RND(26) TF_RND(6)
    x0 += ks1; x1 += ks2 + 1u;
    TF_RND(17) TF_RND(29) TF_RND(16) TF_RND(24)
    x0 += ks2; x1 += ks0 + 2u;
    TF_RND(13) TF_RND(15) TF_RND(26) TF_RND(6)
    x0 += ks0; x1 += ks1 + 3u;
    TF_RND(17) TF_RND(29) TF_RND(16) TF_RND(24)
    x0 += ks1; x1 += ks2 + 4u;
    TF_RND(13) TF_RND(15) TF_RND(26) TF_RND(6)
    x0 += ks2; x1 += ks0 + 5u;
#undef TF_RND
    return x0 ^ x1;
}

// Vectorized fire-and-forget reduction (sm_90+): 4 floats per red op.
__device__ __forceinline__ void red_add_v4(float* addr, float a, float b, float c, float d) {
    asm volatile("red.global.add.v4.f32 [%0], {%1, %2, %3, %4};"
                 :: "l"(addr), "f"(a), "f"(b), "f"(c), "f"(d)
                 : "memory");
}

// ---------------------------------------------------------------------------
__global__ void k_zero(float* __restrict__ p, int n4) {
    int i = blockIdx.x * blockDim.x + threadIdx.x;
    if (i < n4) reinterpret_cast<float4*>(p)[i] = make_float4(0.f, 0.f, 0.f, 0.f);
}

// SpMM pass 1 with fused sparse dropout:
// One warp per x-nnz. Lane 0 hashes the nnz index (Threefry), broadcast.
// keep => scale by 1/0.9; drop => warp exits (no gather, no scatter).
__global__ void k_spmm_drop(const int*   __restrict__ rows,
                            const int*   __restrict__ cols,
                            const float* __restrict__ vals,
                            const float* __restrict__ W,
                            float*       __restrict__ h) {
    int w = (int)((blockIdx.x * blockDim.x + threadIdx.x) >> 5);
    if (w >= NNZ) return;
    int lane = threadIdx.x & 31;

    // mask = floor(0.9f + u) == 1  <=>  (bits>>9) >= 838861
    unsigned int bits = 0;
    if (lane == 0) bits = threefry_xor((unsigned int)w);
    bits = __shfl_sync(0xFFFFFFFFu, bits, 0);
    if ((bits >> 9) < 838861u) return;   // dropped: contributes nothing

    const float INV_KEEP = (float)(1.0 / 0.9);
    float v = __ldg(vals + w) * INV_KEEP;
    int r = __ldg(rows + w);
    int c = __ldg(cols + w);
    const float4* s4 = reinterpret_cast<const float4*>(W + (size_t)c * D_OUT);
    float4 a = __ldg(s4 + lane);
    float* d = h + (size_t)r * D_OUT + lane * 4;
    red_add_v4(d, a.x * v, a.y * v, a.z * v, a.w * v);
}

// SpMM pass 2: one warp per adj-nnz, gather h row, scatter-add to out row.
__global__ void k_spmm(const int*   __restrict__ rows,
                       const int*   __restrict__ cols,
                       const float* __restrict__ vals,
                       const float* __restrict__ src,
                       float*       __restrict__ dst) {
    int w = (int)((blockIdx.x * blockDim.x + threadIdx.x) >> 5);
    if (w >= NNZ) return;
    int lane = threadIdx.x & 31;
    float v = __ldg(vals + w);
    int r = __ldg(rows + w);
    int c = __ldg(cols + w);
    const float4* s4 = reinterpret_cast<const float4*>(src + (size_t)c * D_OUT);
    float4 a = __ldg(s4 + lane);
    float* d = dst + (size_t)r * D_OUT + lane * 4;
    red_add_v4(d, a.x * v, a.y * v, a.z * v, a.w * v);
}

__global__ void k_relu(float* __restrict__ p, int n4) {
    int i = blockIdx.x * blockDim.x + threadIdx.x;
    if (i >= n4) return;
    float4 v = reinterpret_cast<float4*>(p)[i];
    v.x = fmaxf(v.x, 0.f); v.y = fmaxf(v.y, 0.f);
    v.z = fmaxf(v.z, 0.f); v.w = fmaxf(v.w, 0.f);
    reinterpret_cast<float4*>(p)[i] = v;
}

// ---------------------------------------------------------------------------
extern "C" void kernel_launch(void* const* d_in, const int* in_sizes, int n_in,
                              void* d_out, int out_size) {
    const int*   x_rows   = (const int*)  d_in[0];
    const int*   x_cols   = (const int*)  d_in[1];
    const float* x_vals   = (const float*)d_in[2];
    const int*   adj_rows = (const int*)  d_in[3];
    const int*   adj_cols = (const int*)  d_in[4];
    const float* adj_vals = (const float*)d_in[5];
    const float* W        = (const float*)d_in[6];
    float*       out      = (float*)d_out;

    void* hptr;  cudaGetSymbolAddress(&hptr, g_h);
    float* h = (float*)hptr;

    const int HN4 = N_NODES * D_OUT / 4;       // 3.2M float4
    const int ZB  = (HN4 + 255) / 256;

    k_zero<<<ZB, 256>>>(h, HN4);
    k_zero<<<ZB, 256>>>(out, HN4);

    const int SPMM_BLOCKS = (int)(((long long)NNZ * 32 + 255) / 256);  // 400000
    k_spmm_drop<<<SPMM_BLOCKS, 256>>>(x_rows, x_cols, x_vals, W, h);    // h = dropout(x) @ W
    k_spmm<<<SPMM_BLOCKS, 256>>>(adj_rows, adj_cols, adj_vals, h, out); // out = adj @ h
    k_relu<<<ZB, 256>>>(out, HN4);
}

// round 4
// speedup vs baseline: 2.2798x; 2.2798x over previous
#include <cuda_runtime.h>
#include <cuda_bf16.h>

#define N_NODES 100000
#define D_IN    256
#define D_OUT   128
#define NNZ     3200000
#define SCAN_B  1024
#define SCAN_G  98            // ceil(100000/1024)

// ---- static scratch (no allocation allowed) --------------------------------
__device__ float g_h[(size_t)N_NODES * D_OUT];  // 51.2 MB intermediate
__device__ int   g_counts_x[N_NODES];
__device__ int   g_counts_a[N_NODES];
__device__ int   g_offs_x[N_NODES + 1];
__device__ int   g_offs_a[N_NODES + 1];
__device__ int   g_cursor_x[N_NODES];
__device__ int   g_cursor_a[N_NODES];
__device__ int   g_bsum[SCAN_G];
__device__ int   g_boff[SCAN_G];
__device__ int   g_cols_x[NNZ];
__device__ float g_vals_x[NNZ];
__device__ int   g_cols_a[NNZ];
__device__ float g_vals_a[NNZ];

// ---------------------------------------------------------------------------
// Threefry-2x32, JAX partitionable: key=(0,42), ctr=(0,i), out = lane0 ^ lane1
// ---------------------------------------------------------------------------
__device__ __forceinline__ unsigned int threefry_xor(unsigned int ctr) {
    const unsigned int ks0 = 0u, ks1 = 42u;
    const unsigned int ks2 = ks0 ^ ks1 ^ 0x1BD11BDAu;
    unsigned int x0 = ks0;
    unsigned int x1 = ctr + ks1;
#define TF_RND(r) { x0 += x1; x1 = (x1 << (r)) | (x1 >> (32 - (r))); x1 ^= x0; }
    TF_RND(13) TF_RND(15) TF_RND(26) TF_RND(6)
    x0 += ks1; x1 += ks2 + 1u;
    TF_RND(17) TF_RND(29) TF_RND(16) TF_RND(24)
    x0 += ks2; x1 += ks0 + 2u;
    TF_RND(13) TF_RND(15) TF_RND(26) TF_RND(6)
    x0 += ks0; x1 += ks1 + 3u;
    TF_RND(17) TF_RND(29) TF_RND(16) TF_RND(24)
    x0 += ks1; x1 += ks2 + 4u;
    TF_RND(13) TF_RND(15) TF_RND(26) TF_RND(6)
    x0 += ks2; x1 += ks0 + 5u;
#undef TF_RND
    return x0 ^ x1;
}
__device__ __forceinline__ bool kept(unsigned int i) {
    return (threefry_xor(i) >> 9) >= 838861u;   // floor(0.9f + u) == 1
}

// ---------------------------------------------------------------------------
__global__ void k_zero_counts() {
    int i = blockIdx.x * blockDim.x + threadIdx.x;
    if (i < N_NODES) { g_counts_x[i] = 0; g_counts_a[i] = 0; }
}

__global__ void k_hist_x(const int* __restrict__ rows) {
    int i = blockIdx.x * blockDim.x + threadIdx.x;
    if (i >= NNZ) return;
    if (!kept((unsigned int)i)) return;   // dropout fused: dropped never enter CSR
    atomicAdd(&g_counts_x[__ldg(rows + i)], 1);
}
__global__ void k_hist_a(const int* __restrict__ rows) {
    int i = blockIdx.x * blockDim.x + threadIdx.x;
    if (i >= NNZ) return;
    atomicAdd(&g_counts_a[__ldg(rows + i)], 1);
}

// ---- 3-phase exclusive scan over N_NODES counts -> offs[0..N] --------------
__global__ void k_scan1(const int* __restrict__ counts, int* __restrict__ offs) {
    __shared__ int s[SCAN_B];
    int t = threadIdx.x;
    int i = blockIdx.x * SCAN_B + t;
    int v = (i < N_NODES) ? counts[i] : 0;
    s[t] = v;
    __syncthreads();
    #pragma unroll
    for (int d = 1; d < SCAN_B; d <<= 1) {
        int add = (t >= d) ? s[t - d] : 0;
        __syncthreads();
        s[t] += add;
        __syncthreads();
    }
    if (i < N_NODES) offs[i + 1] = s[t];
    if (t == SCAN_B - 1) g_bsum[blockIdx.x] = s[t];
}
__global__ void k_scan2() {
    if (threadIdx.x == 0 && blockIdx.x == 0) {
        int s = 0;
        for (int i = 0; i < SCAN_G; i++) { g_boff[i] = s; s += g_bsum[i]; }
    }
}
__global__ void k_scan3(int* __restrict__ offs) {
    int t = threadIdx.x;
    int i = blockIdx.x * SCAN_B + t;
    if (i < N_NODES) offs[i + 1] += g_boff[blockIdx.x];
    if (i == 0) offs[0] = 0;
}

__global__ void k_cursors() {
    int i = blockIdx.x * blockDim.x + threadIdx.x;
    if (i < N_NODES) { g_cursor_x[i] = g_offs_x[i]; g_cursor_a[i] = g_offs_a[i]; }
}

__global__ void k_scatter_x(const int* __restrict__ rows, const int* __restrict__ cols,
                            const float* __restrict__ vals) {
    int i = blockIdx.x * blockDim.x + threadIdx.x;
    if (i >= NNZ) return;
    if (!kept((unsigned int)i)) return;
    const float INV_KEEP = (float)(1.0 / 0.9);
    int r = __ldg(rows + i);
    int pos = atomicAdd(&g_cursor_x[r], 1);
    g_cols_x[pos] = __ldg(cols + i);
    g_vals_x[pos] = __ldg(vals + i) * INV_KEEP;
}
__global__ void k_scatter_a(const int* __restrict__ rows, const int* __restrict__ cols,
                            const float* __restrict__ vals) {
    int i = blockIdx.x * blockDim.x + threadIdx.x;
    if (i >= NNZ) return;
    int r = __ldg(rows + i);
    int pos = atomicAdd(&g_cursor_a[r], 1);
    g_cols_a[pos] = __ldg(cols + i);
    g_vals_a[pos] = __ldg(vals + i);
}

// ---- row-parallel SpMM: warp per node, lane owns 4 output cols -------------
__global__ void k_row_spmm(const int*   __restrict__ offs,
                           const int*   __restrict__ cols,
                           const float* __restrict__ vals,
                           const float* __restrict__ src,
                           float*       __restrict__ dst,
                           int do_relu) {
    int w = (int)((blockIdx.x * blockDim.x + threadIdx.x) >> 5);
    if (w >= N_NODES) return;
    int lane = threadIdx.x & 31;
    int start = __ldg(offs + w);
    int end   = __ldg(offs + w + 1);

    float4 acc = make_float4(0.f, 0.f, 0.f, 0.f);
    for (int base = start; base < end; base += 32) {
        int m = end - base; if (m > 32) m = 32;
        int   c = 0; float v = 0.f;
        if (lane < m) { c = __ldg(cols + base + lane); v = __ldg(vals + base + lane); }
        #pragma unroll 4
        for (int k = 0; k < m; k++) {
            int   ck = __shfl_sync(0xFFFFFFFFu, c, k);
            float vk = __shfl_sync(0xFFFFFFFFu, v, k);
            float4 a = __ldg(reinterpret_cast<const float4*>(src + (size_t)ck * D_OUT) + lane);
            acc.x = fmaf(a.x, vk, acc.x);
            acc.y = fmaf(a.y, vk, acc.y);
            acc.z = fmaf(a.z, vk, acc.z);
            acc.w = fmaf(a.w, vk, acc.w);
        }
    }
    if (do_relu) {
        acc.x = fmaxf(acc.x, 0.f); acc.y = fmaxf(acc.y, 0.f);
        acc.z = fmaxf(acc.z, 0.f); acc.w = fmaxf(acc.w, 0.f);
    }
    reinterpret_cast<float4*>(dst + (size_t)w * D_OUT)[lane] = acc;
}

// ---------------------------------------------------------------------------
extern "C" void kernel_launch(void* const* d_in, const int* in_sizes, int n_in,
                              void* d_out, int out_size) {
    const int*   x_rows   = (const int*)  d_in[0];
    const int*   x_cols   = (const int*)  d_in[1];
    const float* x_vals   = (const float*)d_in[2];
    const int*   adj_rows = (const int*)  d_in[3];
    const int*   adj_cols = (const int*)  d_in[4];
    const float* adj_vals = (const float*)d_in[5];
    const float* W        = (const float*)d_in[6];
    float*       out      = (float*)d_out;

    void* p;
    cudaGetSymbolAddress(&p, g_h);      float* h      = (float*)p;
    cudaGetSymbolAddress(&p, g_offs_x); int*   offs_x = (int*)p;
    cudaGetSymbolAddress(&p, g_offs_a); int*   offs_a = (int*)p;
    cudaGetSymbolAddress(&p, g_counts_x); int* counts_x = (int*)p;
    cudaGetSymbolAddress(&p, g_counts_a); int* counts_a = (int*)p;
    cudaGetSymbolAddress(&p, g_cols_x); int*   cols_x = (int*)p;
    cudaGetSymbolAddress(&p, g_vals_x); float* vals_x = (float*)p;
    cudaGetSymbolAddress(&p, g_cols_a); int*   cols_a = (int*)p;
    cudaGetSymbolAddress(&p, g_vals_a); float* vals_a = (float*)p;

    const int NBLK   = (N_NODES + 255) / 256;       // node-wise launches
    const int EBLK   = NNZ / 256;                   // edge-wise launches (12500)
    const int WBLK   = (N_NODES * 32 + 255) / 256;  // warp-per-node (12500)

    // CSR build
    k_zero_counts<<<NBLK, 256>>>();
    k_hist_x<<<EBLK, 256>>>(x_rows);
    k_hist_a<<<EBLK, 256>>>(adj_rows);
    k_scan1<<<SCAN_G, SCAN_B>>>(counts_x, offs_x);
    k_scan2<<<1, 32>>>();
    k_scan3<<<SCAN_G, SCAN_B>>>(offs_x);
    k_scan1<<<SCAN_G, SCAN_B>>>(counts_a, offs_a);
    k_scan2<<<1, 32>>>();
    k_scan3<<<SCAN_G, SCAN_B>>>(offs_a);
    k_cursors<<<NBLK, 256>>>();
    k_scatter_x<<<EBLK, 256>>>(x_rows, x_cols, x_vals);
    k_scatter_a<<<EBLK, 256>>>(adj_rows, adj_cols, adj_vals);

    // Pass 1: h = dropout(x) @ W   (W gathers are L1-resident)
    k_row_spmm<<<WBLK, 256>>>(offs_x, cols_x, vals_x, W, h, 0);
    // Pass 2: out = relu(adj @ h)  (h gathers from L2)
    k_row_spmm<<<WBLK, 256>>>(offs_a, cols_a, vals_a, h, out, 1);
}

// round 15
// speedup vs baseline: 3.0846x; 1.3530x over previous
#include <cuda_runtime.h>
#include <cuda_fp16.h>

#define N_NODES 100000
#define D_IN    256
#define D_OUT   128
#define NNZ     3200000
#define TILE    1024
#define NTILES  98            // ceil(100000/1024)

// ---- static scratch (no allocation allowed; zero-initialized at load) ------
__device__ __half        g_h[(size_t)N_NODES * D_OUT];   // 25.6 MB intermediate (fp16)
__device__ int           g_counts[2][N_NODES];           // [0]=x, [1]=adj  (rezeroed by spmm_a)
__device__ int           g_offs[2][N_NODES + 1];
__device__ int           g_cursor[2][N_NODES];
__device__ int           g_bsum[2][NTILES];              // per-tile sums
__device__ unsigned char g_keep[NNZ];                    // dropout keep bits
__device__ int2          g_csr[2][NNZ];                  // packed {col, val_bits}

// ---------------------------------------------------------------------------
// Threefry-2x32, JAX partitionable: key=(0,42), ctr=(0,i), out = lane0 ^ lane1
// ---------------------------------------------------------------------------
__device__ __forceinline__ unsigned int threefry_xor(unsigned int ctr) {
    const unsigned int ks0 = 0u, ks1 = 42u;
    const unsigned int ks2 = ks0 ^ ks1 ^ 0x1BD11BDAu;
    unsigned int x0 = ks0;
    unsigned int x1 = ctr + ks1;
#define TF_RND(r) { x0 += x1; x1 = (x1 << (r)) | (x1 >> (32 - (r))); x1 ^= x0; }
    TF_RND(13) TF_RND(15) TF_RND(26) TF_RND(6)
    x0 += ks1; x1 += ks2 + 1u;
    TF_RND(17) TF_RND(29) TF_RND(16) TF_RND(24)
    x0 += ks2; x1 += ks0 + 2u;
    TF_RND(13) TF_RND(15) TF_RND(26) TF_RND(6)
    x0 += ks0; x1 += ks1 + 3u;
    TF_RND(17) TF_RND(29) TF_RND(16) TF_RND(24)
    x0 += ks1; x1 += ks2 + 4u;
    TF_RND(13) TF_RND(15) TF_RND(26) TF_RND(6)
    x0 += ks2; x1 += ks0 + 5u;
#undef TF_RND
    return x0 ^ x1;
}

// ---------------------------------------------------------------------------
// 1) fused histogram: first NNZ threads do x (with dropout), rest do adj.
//    Requires g_counts == 0 on entry: true at load (static zero-init) and
//    re-established by k_spmm_a each call.
__global__ void k_hist(const int* __restrict__ x_rows, const int* __restrict__ a_rows) {
    int i = blockIdx.x * blockDim.x + threadIdx.x;
    if (i < NNZ) {
        bool keep = (threefry_xor((unsigned int)i) >> 9) >= 838861u;
        g_keep[i] = keep ? 1 : 0;
        if (keep) atomicAdd(&g_counts[0][__ldg(x_rows + i)], 1);
    } else {
        int j = i - NNZ;
        atomicAdd(&g_counts[1][__ldg(a_rows + j)], 1);
    }
}

// 2) scanA: per-tile local inclusive scan; writes offs[i+1] (no base) + tile sum.
__global__ void k_scanA() {
    __shared__ int s_wsum[32];
    int tid = threadIdx.x;
    int arr  = (blockIdx.x >= NTILES) ? 1 : 0;
    int tile = blockIdx.x - arr * NTILES;
    int i = tile * TILE + tid;
    int cnt = (i < N_NODES) ? g_counts[arr][i] : 0;

    int lane = tid & 31, wid = tid >> 5;
    int v = cnt;
    #pragma unroll
    for (int d = 1; d < 32; d <<= 1) {
        int n = __shfl_up_sync(0xFFFFFFFFu, v, d);
        if (lane >= d) v += n;
    }
    if (lane == 31) s_wsum[wid] = v;
    __syncthreads();
    if (wid == 0) {
        int s = s_wsum[lane];
        #pragma unroll
        for (int d = 1; d < 32; d <<= 1) {
            int n = __shfl_up_sync(0xFFFFFFFFu, s, d);
            if (lane >= d) s += n;
        }
        s_wsum[lane] = s;
    }
    __syncthreads();
    int incl = v + (wid > 0 ? s_wsum[wid - 1] : 0);
    if (i < N_NODES) g_offs[arr][i + 1] = incl;        // local (tile-relative)
    if (tid == TILE - 1) g_bsum[arr][tile] = incl;
}

// 3) scanB: each block redundantly serial-sums tile sums (<=98) for its base,
//    then finalizes offs and writes cursors. No inter-block communication.
__global__ void k_scanB() {
    __shared__ int s_base;
    int tid = threadIdx.x;
    int arr  = (blockIdx.x >= NTILES) ? 1 : 0;
    int tile = blockIdx.x - arr * NTILES;
    if (tid == 0) {
        int b = 0;
        for (int t = 0; t < tile; t++) b += g_bsum[arr][t];
        s_base = b;
    }
    __syncthreads();
    int base = s_base;
    int i = tile * TILE + tid;
    if (i < N_NODES) {
        int val = g_offs[arr][i + 1] + base;           // final inclusive
        g_offs[arr][i + 1] = val;
        g_cursor[arr][i]   = val - g_counts[arr][i];   // exclusive start
    }
    if (i == 0) g_offs[arr][0] = 0;
}

// 4) fused scatter into packed CSR (one 8B store per nnz)
__global__ void k_scatter(const int* __restrict__ x_rows, const int* __restrict__ x_cols,
                          const float* __restrict__ x_vals,
                          const int* __restrict__ a_rows, const int* __restrict__ a_cols,
                          const float* __restrict__ a_vals) {
    int i = blockIdx.x * blockDim.x + threadIdx.x;
    if (i < NNZ) {
        if (!g_keep[i]) return;
        const float INV_KEEP = (float)(1.0 / 0.9);
        int r = __ldg(x_rows + i);
        int pos = atomicAdd(&g_cursor[0][r], 1);
        g_csr[0][pos] = make_int2(__ldg(x_cols + i),
                                  __float_as_int(__ldg(x_vals + i) * INV_KEEP));
    } else {
        int j = i - NNZ;
        int r = __ldg(a_rows + j);
        int pos = atomicAdd(&g_cursor[1][r], 1);
        g_csr[1][pos] = make_int2(__ldg(a_cols + j), __float_as_int(__ldg(a_vals + j)));
    }
}

// 5) pass 1: warp per node, gather fp32 W rows, accumulate fp32, store fp16 h
__global__ void k_spmm_x(const int*  __restrict__ offs,
                         const int2* __restrict__ csr,
                         const float* __restrict__ W,
                         __half*      __restrict__ h) {
    int w = (int)((blockIdx.x * blockDim.x + threadIdx.x) >> 5);
    if (w >= N_NODES) return;
    int lane = threadIdx.x & 31;
    int start = __ldg(offs + w);
    int end   = __ldg(offs + w + 1);

    float4 acc = make_float4(0.f, 0.f, 0.f, 0.f);
    for (int base = start; base < end; base += 32) {
        int m = end - base; if (m > 32) m = 32;
        long long cv = 0;
        if (lane < m)
            cv = __ldg(reinterpret_cast<const long long*>(csr) + base + lane);
        #pragma unroll 4
        for (int k = 0; k < m; k++) {
            long long p = __shfl_sync(0xFFFFFFFFu, cv, k);
            int   ck = (int)(unsigned int)p;
            float vk = __int_as_float((int)(p >> 32));
            float4 a = __ldg(reinterpret_cast<const float4*>(W + (size_t)ck * D_OUT) + lane);
            acc.x = fmaf(a.x, vk, acc.x);
            acc.y = fmaf(a.y, vk, acc.y);
            acc.z = fmaf(a.z, vk, acc.z);
            acc.w = fmaf(a.w, vk, acc.w);
        }
    }
    __half2 h01 = __floats2half2_rn(acc.x, acc.y);
    __half2 h23 = __floats2half2_rn(acc.z, acc.w);
    uint2 packed;
    packed.x = *reinterpret_cast<unsigned int*>(&h01);   // __half2 is a 32-bit object
    packed.y = *reinterpret_cast<unsigned int*>(&h23);
    reinterpret_cast<uint2*>(h + (size_t)w * D_OUT)[lane] = packed;
}

// 6) pass 2: warp per node, gather fp16 h rows, accumulate fp32, relu, store fp32.
//    Also rezeroes g_counts for the next replay (counts are dead after scanB).
__global__ void k_spmm_a(const int*  __restrict__ offs,
                         const int2* __restrict__ csr,
                         const __half* __restrict__ h,
                         float*       __restrict__ out) {
    int g = blockIdx.x * blockDim.x + threadIdx.x;
    if (g < 2 * N_NODES) ((int*)g_counts)[g] = 0;      // prep next replay

    int w = (int)(g >> 5);
    if (w >= N_NODES) return;
    int lane = threadIdx.x & 31;
    int start = __ldg(offs + w);
    int end   = __ldg(offs + w + 1);

    float4 acc = make_float4(0.f, 0.f, 0.f, 0.f);
    for (int base = start; base < end; base += 32) {
        int m = end - base; if (m > 32) m = 32;
        long long cv = 0;
        if (lane < m)
            cv = __ldg(reinterpret_cast<const long long*>(csr) + base + lane);
        #pragma unroll 4
        for (int k = 0; k < m; k++) {
            long long p = __shfl_sync(0xFFFFFFFFu, cv, k);
            int   ck = (int)(unsigned int)p;
            float vk = __int_as_float((int)(p >> 32));
            uint2 raw = __ldg(reinterpret_cast<const uint2*>(h + (size_t)ck * D_OUT) + lane);
            float2 f01 = __half22float2(*reinterpret_cast<__half2*>(&raw.x));
            float2 f23 = __half22float2(*reinterpret_cast<__half2*>(&raw.y));
            acc.x = fmaf(f01.x, vk, acc.x);
            acc.y = fmaf(f01.y, vk, acc.y);
            acc.z = fmaf(f23.x, vk, acc.z);
            acc.w = fmaf(f23.y, vk, acc.w);
        }
    }
    acc.x = fmaxf(acc.x, 0.f); acc.y = fmaxf(acc.y, 0.f);
    acc.z = fmaxf(acc.z, 0.f); acc.w = fmaxf(acc.w, 0.f);
    reinterpret_cast<float4*>(out + (size_t)w * D_OUT)[lane] = acc;
}

// ---------------------------------------------------------------------------
extern "C" void kernel_launch(void* const* d_in, const int* in_sizes, int n_in,
                              void* d_out, int out_size) {
    const int*   x_rows   = (const int*)  d_in[0];
    const int*   x_cols   = (const int*)  d_in[1];
    const float* x_vals   = (const float*)d_in[2];
    const int*   adj_rows = (const int*)  d_in[3];
    const int*   adj_cols = (const int*)  d_in[4];
    const float* adj_vals = (const float*)d_in[5];
    const float* W        = (const float*)d_in[6];
    float*       out      = (float*)d_out;

    void* p;
    cudaGetSymbolAddress(&p, g_h);    __half* h    = (__half*)p;
    cudaGetSymbolAddress(&p, g_offs); int*   offs0 = (int*)p;              // [2][N+1]
    cudaGetSymbolAddress(&p, g_csr);  int2*  csr0  = (int2*)p;             // [2][NNZ]
    int*  offs_x = offs0;
    int*  offs_a = offs0 + (N_NODES + 1);
    int2* csr_x  = csr0;
    int2* csr_a  = csr0 + NNZ;

    const int EBLK2 = 2 * NNZ / 256;                  // 25000
    const int WBLK  = (N_NODES * 32 + 255) / 256;     // 12500

    k_hist<<<EBLK2, 256>>>(x_rows, adj_rows);                             // 1
    k_scanA<<<2 * NTILES, TILE>>>();                                      // 2
    k_scanB<<<2 * NTILES, TILE>>>();                                      // 3
    k_scatter<<<EBLK2, 256>>>(x_rows, x_cols, x_vals,
                              adj_rows, adj_cols, adj_vals);              // 4
    k_spmm_x<<<WBLK, 256>>>(offs_x, csr_x, W, h);                         // 5
    k_spmm_a<<<WBLK, 256>>>(offs_a, csr_a, h, out);                       // 6 (profiled)
}

// round 17
// speedup vs baseline: 3.0857x; 1.0004x over previous
#include <cuda_runtime.h>
#include <cuda_fp16.h>

#define N_NODES 100000
#define D_IN    256
#define D_OUT   128
#define NNZ     3200000
#define TILE    1024
#define NTILES  98            // ceil(100000/1024)
#define NNZ4    (NNZ / 4)     // 800000

// ---- static scratch (no allocation allowed; zero-initialized at load) ------
__device__ __half        g_h[(size_t)N_NODES * D_OUT];   // 25.6 MB intermediate (fp16)
__device__ int           g_counts[2][N_NODES];           // [0]=x, [1]=adj  (rezeroed by spmm_a)
__device__ int           g_offs[2][N_NODES + 1];
__device__ int           g_cursor[2][N_NODES];
__device__ int           g_bsum[2][NTILES];              // per-tile sums
__device__ uchar4        g_keep4[NNZ4];                  // dropout keep bits, 4 per word
__device__ int2          g_csr[2][NNZ];                  // packed {col, val_bits}

// ---------------------------------------------------------------------------
// Threefry-2x32, JAX partitionable: key=(0,42), ctr=(0,i), out = lane0 ^ lane1
// ---------------------------------------------------------------------------
__device__ __forceinline__ unsigned int threefry_xor(unsigned int ctr) {
    const unsigned int ks0 = 0u, ks1 = 42u;
    const unsigned int ks2 = ks0 ^ ks1 ^ 0x1BD11BDAu;
    unsigned int x0 = ks0;
    unsigned int x1 = ctr + ks1;
#define TF_RND(r) { x0 += x1; x1 = (x1 << (r)) | (x1 >> (32 - (r))); x1 ^= x0; }
    TF_RND(13) TF_RND(15) TF_RND(26) TF_RND(6)
    x0 += ks1; x1 += ks2 + 1u;
    TF_RND(17) TF_RND(29) TF_RND(16) TF_RND(24)
    x0 += ks2; x1 += ks0 + 2u;
    TF_RND(13) TF_RND(15) TF_RND(26) TF_RND(6)
    x0 += ks0; x1 += ks1 + 3u;
    TF_RND(17) TF_RND(29) TF_RND(16) TF_RND(24)
    x0 += ks1; x1 += ks2 + 4u;
    TF_RND(13) TF_RND(15) TF_RND(26) TF_RND(6)
    x0 += ks2; x1 += ks0 + 5u;
#undef TF_RND
    return x0 ^ x1;
}
__device__ __forceinline__ bool tf_keep(unsigned int i) {
    return (threefry_xor(i) >> 9) >= 838861u;   // floor(0.9f + u) == 1
}

// ---------------------------------------------------------------------------
// 1) fused histogram, 4 items/thread (vectorized loads, 4 independent atomics).
//    Threads [0, NNZ4): x items 4t..4t+3 (computes+stores keep). Rest: adj.
__global__ void k_hist(const int* __restrict__ x_rows, const int* __restrict__ a_rows) {
    int t = blockIdx.x * blockDim.x + threadIdx.x;
    if (t < NNZ4) {
        int4 r = __ldg(reinterpret_cast<const int4*>(x_rows) + t);
        unsigned int b = 4u * (unsigned int)t;
        bool k0 = tf_keep(b), k1 = tf_keep(b + 1u), k2 = tf_keep(b + 2u), k3 = tf_keep(b + 3u);
        g_keep4[t] = make_uchar4(k0, k1, k2, k3);
        if (k0) atomicAdd(&g_counts[0][r.x], 1);
        if (k1) atomicAdd(&g_counts[0][r.y], 1);
        if (k2) atomicAdd(&g_counts[0][r.z], 1);
        if (k3) atomicAdd(&g_counts[0][r.w], 1);
    } else if (t < 2 * NNZ4) {
        int4 r = __ldg(reinterpret_cast<const int4*>(a_rows) + (t - NNZ4));
        atomicAdd(&g_counts[1][r.x], 1);
        atomicAdd(&g_counts[1][r.y], 1);
        atomicAdd(&g_counts[1][r.z], 1);
        atomicAdd(&g_counts[1][r.w], 1);
    }
}

// 2) scanA: per-tile local inclusive scan; writes offs[i+1] (no base) + tile sum.
__global__ void k_scanA() {
    __shared__ int s_wsum[32];
    int tid = threadIdx.x;
    int arr  = (blockIdx.x >= NTILES) ? 1 : 0;
    int tile = blockIdx.x - arr * NTILES;
    int i = tile * TILE + tid;
    int cnt = (i < N_NODES) ? g_counts[arr][i] : 0;

    int lane = tid & 31, wid = tid >> 5;
    int v = cnt;
    #pragma unroll
    for (int d = 1; d < 32; d <<= 1) {
        int n = __shfl_up_sync(0xFFFFFFFFu, v, d);
        if (lane >= d) v += n;
    }
    if (lane == 31) s_wsum[wid] = v;
    __syncthreads();
    if (wid == 0) {
        int s = s_wsum[lane];
        #pragma unroll
        for (int d = 1; d < 32; d <<= 1) {
            int n = __shfl_up_sync(0xFFFFFFFFu, s, d);
            if (lane >= d) s += n;
        }
        s_wsum[lane] = s;
    }
    __syncthreads();
    int incl = v + (wid > 0 ? s_wsum[wid - 1] : 0);
    if (i < N_NODES) g_offs[arr][i + 1] = incl;        // local (tile-relative)
    if (tid == TILE - 1) g_bsum[arr][tile] = incl;
}

// 3) scanB: each block redundantly serial-sums tile sums (<=98) for its base,
//    then finalizes offs and writes cursors. No inter-block communication.
__global__ void k_scanB() {
    __shared__ int s_base;
    int tid = threadIdx.x;
    int arr  = (blockIdx.x >= NTILES) ? 1 : 0;
    int tile = blockIdx.x - arr * NTILES;
    if (tid == 0) {
        int b = 0;
        for (int t = 0; t < tile; t++) b += g_bsum[arr][t];
        s_base = b;
    }
    __syncthreads();
    int base = s_base;
    int i = tile * TILE + tid;
    if (i < N_NODES) {
        int val = g_offs[arr][i + 1] + base;           // final inclusive
        g_offs[arr][i + 1] = val;
        g_cursor[arr][i]   = val - g_counts[arr][i];   // exclusive start
    }
    if (i == 0) g_offs[arr][0] = 0;
}

// 4) fused scatter, 4 items/thread: vectorized reads, 4 independent
//    atomic->store chains per thread (MLP=4).
__global__ void k_scatter(const int* __restrict__ x_rows, const int* __restrict__ x_cols,
                          const float* __restrict__ x_vals,
                          const int* __restrict__ a_rows, const int* __restrict__ a_cols,
                          const float* __restrict__ a_vals) {
    int t = blockIdx.x * blockDim.x + threadIdx.x;
    if (t < NNZ4) {
        uchar4 kp = g_keep4[t];
        int4   r  = __ldg(reinterpret_cast<const int4*>(x_rows) + t);
        int4   c  = __ldg(reinterpret_cast<const int4*>(x_cols) + t);
        float4 v  = __ldg(reinterpret_cast<const float4*>(x_vals) + t);
        const float INV_KEEP = (float)(1.0 / 0.9);
        if (kp.x) { int p = atomicAdd(&g_cursor[0][r.x], 1);
                    g_csr[0][p] = make_int2(c.x, __float_as_int(v.x * INV_KEEP)); }
        if (kp.y) { int p = atomicAdd(&g_cursor[0][r.y], 1);
                    g_csr[0][p] = make_int2(c.y, __float_as_int(v.y * INV_KEEP)); }
        if (kp.z) { int p = atomicAdd(&g_cursor[0][r.z], 1);
                    g_csr[0][p] = make_int2(c.z, __float_as_int(v.z * INV_KEEP)); }
        if (kp.w) { int p = atomicAdd(&g_cursor[0][r.w], 1);
                    g_csr[0][p] = make_int2(c.w, __float_as_int(v.w * INV_KEEP)); }
    } else if (t < 2 * NNZ4) {
        int j = t - NNZ4;
        int4   r = __ldg(reinterpret_cast<const int4*>(a_rows) + j);
        int4   c = __ldg(reinterpret_cast<const int4*>(a_cols) + j);
        float4 v = __ldg(reinterpret_cast<const float4*>(a_vals) + j);
        { int p = atomicAdd(&g_cursor[1][r.x], 1); g_csr[1][p] = make_int2(c.x, __float_as_int(v.x)); }
        { int p = atomicAdd(&g_cursor[1][r.y], 1); g_csr[1][p] = make_int2(c.y, __float_as_int(v.y)); }
        { int p = atomicAdd(&g_cursor[1][r.z], 1); g_csr[1][p] = make_int2(c.z, __float_as_int(v.z)); }
        { int p = atomicAdd(&g_cursor[1][r.w], 1); g_csr[1][p] = make_int2(c.w, __float_as_int(v.w)); }
    }
}

// 5) pass 1: warp per node, gather fp32 W rows, accumulate fp32, store fp16 h
__global__ void k_spmm_x(const int*  __restrict__ offs,
                         const int2* __restrict__ csr,
                         const float* __restrict__ W,
                         __half*      __restrict__ h) {
    int w = (int)((blockIdx.x * blockDim.x + threadIdx.x) >> 5);
    if (w >= N_NODES) return;
    int lane = threadIdx.x & 31;
    int start = __ldg(offs + w);
    int end   = __ldg(offs + w + 1);

    float4 acc = make_float4(0.f, 0.f, 0.f, 0.f);
    for (int base = start; base < end; base += 32) {
        int m = end - base; if (m > 32) m = 32;
        long long cv = 0;
        if (lane < m)
            cv = __ldg(reinterpret_cast<const long long*>(csr) + base + lane);
        #pragma unroll 4
        for (int k = 0; k < m; k++) {
            long long p = __shfl_sync(0xFFFFFFFFu, cv, k);
            int   ck = (int)(unsigned int)p;
            float vk = __int_as_float((int)(p >> 32));
            float4 a = __ldg(reinterpret_cast<const float4*>(W + (size_t)ck * D_OUT) + lane);
            acc.x = fmaf(a.x, vk, acc.x);
            acc.y = fmaf(a.y, vk, acc.y);
            acc.z = fmaf(a.z, vk, acc.z);
            acc.w = fmaf(a.w, vk, acc.w);
        }
    }
    __half2 h01 = __floats2half2_rn(acc.x, acc.y);
    __half2 h23 = __floats2half2_rn(acc.z, acc.w);
    uint2 packed;
    packed.x = *reinterpret_cast<unsigned int*>(&h01);   // __half2 is a 32-bit object
    packed.y = *reinterpret_cast<unsigned int*>(&h23);
    reinterpret_cast<uint2*>(h + (size_t)w * D_OUT)[lane] = packed;
}

// 6) pass 2: warp per node, gather fp16 h rows, accumulate fp32, relu, store fp32.
//    Also rezeroes g_counts for the next replay (counts are dead after scanB).
__global__ void k_spmm_a(const int*  __restrict__ offs,
                         const int2* __restrict__ csr,
                         const __half* __restrict__ h,
                         float*       __restrict__ out) {
    int g = blockIdx.x * blockDim.x + threadIdx.x;
    if (g < 2 * N_NODES) ((int*)g_counts)[g] = 0;      // prep next replay

    int w = (int)(g >> 5);
    if (w >= N_NODES) return;
    int lane = threadIdx.x & 31;
    int start = __ldg(offs + w);
    int end   = __ldg(offs + w + 1);

    float4 acc = make_float4(0.f, 0.f, 0.f, 0.f);
    for (int base = start; base < end; base += 32) {
        int m = end - base; if (m > 32) m = 32;
        long long cv = 0;
        if (lane < m)
            cv = __ldg(reinterpret_cast<const long long*>(csr) + base + lane);
        #pragma unroll 4
        for (int k = 0; k < m; k++) {
            long long p = __shfl_sync(0xFFFFFFFFu, cv, k);
            int   ck = (int)(unsigned int)p;
            float vk = __int_as_float((int)(p >> 32));
            uint2 raw = __ldg(reinterpret_cast<const uint2*>(h + (size_t)ck * D_OUT) + lane);
            float2 f01 = __half22float2(*reinterpret_cast<__half2*>(&raw.x));
            float2 f23 = __half22float2(*reinterpret_cast<__half2*>(&raw.y));
            acc.x = fmaf(f01.x, vk, acc.x);
            acc.y = fmaf(f01.y, vk, acc.y);
            acc.z = fmaf(f23.x, vk, acc.z);
            acc.w = fmaf(f23.y, vk, acc.w);
        }
    }
    acc.x = fmaxf(acc.x, 0.f); acc.y = fmaxf(acc.y, 0.f);
    acc.z = fmaxf(acc.z, 0.f); acc.w = fmaxf(acc.w, 0.f);
    reinterpret_cast<float4*>(out + (size_t)w * D_OUT)[lane] = acc;
}

// ---------------------------------------------------------------------------
extern "C" void kernel_launch(void* const* d_in, const int* in_sizes, int n_in,
                              void* d_out, int out_size) {
    const int*   x_rows   = (const int*)  d_in[0];
    const int*   x_cols   = (const int*)  d_in[1];
    const float* x_vals   = (const float*)d_in[2];
    const int*   adj_rows = (const int*)  d_in[3];
    const int*   adj_cols = (const int*)  d_in[4];
    const float* adj_vals = (const float*)d_in[5];
    const float* W        = (const float*)d_in[6];
    float*       out      = (float*)d_out;

    void* p;
    cudaGetSymbolAddress(&p, g_h);    __half* h    = (__half*)p;
    cudaGetSymbolAddress(&p, g_offs); int*   offs0 = (int*)p;              // [2][N+1]
    cudaGetSymbolAddress(&p, g_csr);  int2*  csr0  = (int2*)p;             // [2][NNZ]
    int*  offs_x = offs0;
    int*  offs_a = offs0 + (N_NODES + 1);
    int2* csr_x  = csr0;
    int2* csr_a  = csr0 + NNZ;

    const int QBLK = (2 * NNZ4 + 255) / 256;          // 6250 (4 items/thread)
    const int WBLK = (N_NODES * 32 + 255) / 256;      // 12500

    k_hist<<<QBLK, 256>>>(x_rows, adj_rows);                              // 1
    k_scanA<<<2 * NTILES, TILE>>>();                                      // 2
    k_scanB<<<2 * NTILES, TILE>>>();                                      // 3
    k_scatter<<<QBLK, 256>>>(x_rows, x_cols, x_vals,
                             adj_rows, adj_cols, adj_vals);               // 4
    k_spmm_x<<<WBLK, 256>>>(offs_x, csr_x, W, h);                         // 5
    k_spmm_a<<<WBLK, 256>>>(offs_a, csr_a, h, out);                       // 6
}